// round 13
// baseline (speedup 1.0000x reference)
#include <cuda_runtime.h>
#include <math.h>

#define T_FULL 65536
#define NB 4
#define CH 32
#define LL 256
#define HH 64
#define KC 24576

// -------- scratch (static device allocations; allowed) --------
__device__ float g_hA[NB*CH*T_FULL];
__device__ float g_hB[NB*CH*T_FULL];
__device__ float g_y [NB*CH*T_FULL];
__device__ float g_kp0[NB*HH*LL];
__device__ float g_kh[NB*LL*KC];     // transposed: [b][l][kc]
__device__ float g_bh[NB*LL*256];    // transposed: [b][l][bc]

__device__ __forceinline__ float lrelu(float v) { return v >= 0.f ? v : 0.2f * v; }

// ---- packed f32x2 helpers (SASS FFMA2; IEEE-identical to 2x fmaf) ----------
typedef unsigned long long u64t;
__device__ __forceinline__ u64t pk2(float lo, float hi) {
    u64t r; asm("mov.b64 %0, {%1, %2};" : "=l"(r) : "f"(lo), "f"(hi)); return r;
}
__device__ __forceinline__ u64t ffma2(u64t a, u64t b, u64t c) {
    u64t d; asm("fma.rn.f32x2 %0, %1, %2, %3;" : "=l"(d) : "l"(a), "l"(b), "l"(c));
    return d;
}
__device__ __forceinline__ void upk2(u64t v, float& lo, float& hi) {
    asm("mov.b64 {%0, %1}, %2;" : "=f"(lo), "=f"(hi) : "l"(v));
}

// ======== conv_transpose1d (stride 8, k=16, pad 4): 8 outputs/thread ========
__global__ void __launch_bounds__(256) k_convt(const float* __restrict__ x,
        const float* __restrict__ w, const float* __restrict__ bias,
        float* __restrict__ out) {
    int gid = blockIdx.x * 256 + threadIdx.x;
    int tg = gid & 8191;
    int o  = (gid >> 13) & 31;
    int b  = gid >> 18;
    float acc[8];
    float bv = bias[o];
    #pragma unroll
    for (int j = 0; j < 8; j++) acc[j] = bv;
    const float* xb = x + (b * CH) * 8192;
    bool hm = (tg > 0), hp = (tg < 8191);
    #pragma unroll
    for (int i = 0; i < 32; i++) {
        const float* xr = xb + i * 8192 + tg;
        float x0 = xr[0];
        float xm = hm ? xr[-1] : 0.f;
        float xp = hp ? xr[1]  : 0.f;
        const float* wr = w + (i * 32 + o) * 16;
        #pragma unroll
        for (int j = 0; j < 4; j++)
            acc[j] = fmaf(x0, wr[j + 4], fmaf(xm, wr[j + 12], acc[j]));
        #pragma unroll
        for (int j = 4; j < 8; j++)
            acc[j] = fmaf(xp, wr[j - 4], fmaf(x0, wr[j + 4], acc[j]));
    }
    float4* dst = (float4*)(out + ((long)(b * 32 + o)) * T_FULL + tg * 8);
    dst[0] = make_float4(acc[0], acc[1], acc[2], acc[3]);
    dst[1] = make_float4(acc[4], acc[5], acc[6], acc[7]);
}

// ======== fused kernel-predictor front end: in-conv + 3 residual blocks ======
__global__ void __launch_bounds__(256) k_kpf(const float* __restrict__ spec,
        const float* __restrict__ kin_w, const float* __restrict__ kin_b,
        const float* __restrict__ w1, const float* __restrict__ b1,
        const float* __restrict__ w2, const float* __restrict__ b2,
        float* __restrict__ out) {
    __shared__ float S[100 * 37];
    __shared__ float A[64 * 36];
    __shared__ float Bm[64 * 36];
    int b = blockIdx.y;
    int lbase = blockIdx.x * 16 - 8;
    int tid = threadIdx.x;
    for (int i = tid; i < 100 * 37; i += 256) S[i] = 0.f;
    for (int i = tid; i < 64 * 36; i += 256) { A[i] = 0.f; Bm[i] = 0.f; }
    __syncthreads();
    for (int i = tid; i < 100 * 32; i += 256) {
        int c = i >> 5, p = i & 31;
        int l = lbase + p;
        if ((unsigned)l < 256u) S[c * 37 + p + 2] = spec[(b * 100 + c) * 256 + l];
    }
    __syncthreads();
    int o = tid >> 2, pq = tid & 3;
    float acc[8];
    {
        float bv = kin_b[o];
        #pragma unroll
        for (int j = 0; j < 8; j++) acc[j] = bv;
        for (int c = 0; c < 100; c++) {
            const float* wr = kin_w + (o * 100 + c) * 5;
            const float* sr = S + c * 37;
            #pragma unroll
            for (int k = 0; k < 5; k++) {
                float wv = wr[k];
                #pragma unroll
                for (int j = 0; j < 8; j++) acc[j] += sr[pq + 4 * j + k] * wv;
            }
        }
        #pragma unroll
        for (int j = 0; j < 8; j++) {
            int p = pq + 4 * j, l = lbase + p;
            A[o * 36 + p + 1] = ((unsigned)l < 256u) ? acc[j] : 0.f;
        }
    }
    __syncthreads();
    for (int it = 0; it < 3; it++) {
        {
            float bv = b1[it * 64 + o];
            #pragma unroll
            for (int j = 0; j < 8; j++) acc[j] = bv;
            const float* wbase = w1 + it * 64 * 64 * 3 + o * 64 * 3;
            for (int c = 0; c < 64; c++) {
                const float* wr = wbase + c * 3;
                const float* ar = A + c * 36;
                #pragma unroll
                for (int k = 0; k < 3; k++) {
                    float wv = wr[k];
                    #pragma unroll
                    for (int j = 0; j < 8; j++) acc[j] += ar[pq + 4 * j + k] * wv;
                }
            }
            #pragma unroll
            for (int j = 0; j < 8; j++) {
                int p = pq + 4 * j, l = lbase + p;
                Bm[o * 36 + p + 1] = ((unsigned)l < 256u) ? lrelu(acc[j]) : 0.f;
            }
        }
        __syncthreads();
        {
            float bv = b2[it * 64 + o];
            #pragma unroll
            for (int j = 0; j < 8; j++) acc[j] = bv;
            const float* wbase = w2 + it * 64 * 64 * 3 + o * 64 * 3;
            for (int c = 0; c < 64; c++) {
                const float* wr = wbase + c * 3;
                const float* br = Bm + c * 36;
                #pragma unroll
                for (int k = 0; k < 3; k++) {
                    float wv = wr[k];
                    #pragma unroll
                    for (int j = 0; j < 8; j++) acc[j] += br[pq + 4 * j + k] * wv;
                }
            }
            #pragma unroll
            for (int j = 0; j < 8; j++) {
                int p = pq + 4 * j, l = lbase + p;
                float v = lrelu(acc[j]) + A[o * 36 + p + 1];
                A[o * 36 + p + 1] = ((unsigned)l < 256u) ? v : 0.f;
            }
        }
        __syncthreads();
    }
    #pragma unroll
    for (int j = 0; j < 8; j++) {
        int p = pq + 4 * j;
        if (p >= 8 && p < 24)
            out[(b * 64 + o) * 256 + lbase + p] = A[o * 36 + p + 1];
    }
}

// ===== kern conv: 512 threads (R11 base) + transposed-W LDS.128 broadcast ===
// Wt[(ci*3+k)*64 + co_local]: each thread's 4 row-weights = one float4, all
// lanes same address (broadcast, 1 crossbar cycle). Same values/order ->
// bit-identical results.
__global__ void __launch_bounds__(512, 2) k_kern(const float* __restrict__ h,
        const float* __restrict__ w, const float* __restrict__ bias,
        float* __restrict__ outT) {
    extern __shared__ float sm[];
    float* Xs = sm;                    // 64*258 = 16512 f
    float* Wt = sm + 64 * 258;         // 192*64 = 12288 f (transposed)
    float* St = sm;                    // 256*65 (aliased)
    int b = blockIdx.y;
    int r0 = blockIdx.x * 64;
    int tid = threadIdx.y * 32 + threadIdx.x;
    const float* hb = h + b * 64 * 256;
    for (int i = tid; i < 64 * 258; i += 512) {
        int ci = i / 258, p = i - ci * 258;
        int lp = p - 1;
        Xs[i] = ((unsigned)lp < 256u) ? hb[ci * 256 + lp] : 0.f;
    }
    const float* wsrc = w + (long)r0 * 192;
    for (int i = tid; i < 64 * 192; i += 512) {
        int r = i / 192, c = i - r * 192;
        Wt[c * 64 + r] = wsrc[i];
    }
    __syncthreads();
    int tx = threadIdx.x, ty = threadIdx.y;   // ty in 0..15
    u64t acc2[4][4];
    #pragma unroll
    for (int jr = 0; jr < 4; jr++) {
        float bv = bias[r0 + ty * 4 + jr];
        u64t bp = pk2(bv, bv);
        #pragma unroll
        for (int q = 0; q < 4; q++) acc2[jr][q] = bp;
    }
    for (int ci = 0; ci < 64; ci++) {
        const float* xrow = Xs + ci * 258 + tx;
        const float* wrow = Wt + ci * 3 * 64 + ty * 4;
        #pragma unroll
        for (int k = 0; k < 3; k++) {
            u64t x2[4];
            #pragma unroll
            for (int q = 0; q < 4; q++)
                x2[q] = pk2(xrow[64 * q + k], xrow[64 * q + 32 + k]);
            float4 wv = *(const float4*)(wrow + k * 64);
            u64t w2[4];
            w2[0] = pk2(wv.x, wv.x); w2[1] = pk2(wv.y, wv.y);
            w2[2] = pk2(wv.z, wv.z); w2[3] = pk2(wv.w, wv.w);
            #pragma unroll
            for (int jr = 0; jr < 4; jr++)
                #pragma unroll
                for (int q = 0; q < 4; q++)
                    acc2[jr][q] = ffma2(w2[jr], x2[q], acc2[jr][q]);
        }
    }
    __syncthreads();
    #pragma unroll
    for (int jr = 0; jr < 4; jr++)
        #pragma unroll
        for (int q = 0; q < 4; q++) {
            float lo, hi;
            upk2(acc2[jr][q], lo, hi);
            St[(tx + 64 * q) * 65 + ty * 4 + jr] = lo;
            St[(tx + 64 * q + 32) * 65 + ty * 4 + jr] = hi;
        }
    __syncthreads();
    float* dst = outT + (long)b * 256 * KC + r0;
    for (int i = tid; i < 64 * 256; i += 512) {
        int l = i >> 6, kc = i & 63;
        dst[(long)l * KC + kc] = St[l * 65 + kc];
    }
}

// ===== bias conv as tiled GEMM (unchanged, proven) ==========================
__global__ void __launch_bounds__(256) k_biasg(const float* __restrict__ h,
        const float* __restrict__ w, const float* __restrict__ bias,
        float* __restrict__ outT) {
    extern __shared__ float sm[];
    float* Xs = sm;                    // 64*258
    float* Ws = sm + 64 * 258;         // 32*192
    float* St = sm;                    // 256*33 (aliased)
    int b = blockIdx.y;
    int r0 = blockIdx.x * 32;
    int tid = threadIdx.y * 32 + threadIdx.x;
    const float* hb = h + b * 64 * 256;
    for (int i = tid; i < 64 * 258; i += 256) {
        int ci = i / 258, p = i - ci * 258;
        int lp = p - 1;
        Xs[i] = ((unsigned)lp < 256u) ? hb[ci * 256 + lp] : 0.f;
    }
    const float* wsrc = w + (long)r0 * 192;
    for (int i = tid; i < 32 * 192; i += 256) Ws[i] = wsrc[i];
    __syncthreads();
    int tx = threadIdx.x, ty = threadIdx.y;
    float acc[4][8];
    #pragma unroll
    for (int jr = 0; jr < 4; jr++) {
        float bv = bias[r0 + ty * 4 + jr];
        #pragma unroll
        for (int jc = 0; jc < 8; jc++) acc[jr][jc] = bv;
    }
    for (int ci = 0; ci < 64; ci++) {
        const float* xrow = Xs + ci * 258 + tx;
        const float* wcol = Ws + ty * 4 * 192 + ci * 3;
        #pragma unroll
        for (int k = 0; k < 3; k++) {
            float xv[8], wv[4];
            #pragma unroll
            for (int jc = 0; jc < 8; jc++) xv[jc] = xrow[32 * jc + k];
            #pragma unroll
            for (int jr = 0; jr < 4; jr++) wv[jr] = wcol[jr * 192 + k];
            #pragma unroll
            for (int jr = 0; jr < 4; jr++)
                #pragma unroll
                for (int jc = 0; jc < 8; jc++)
                    acc[jr][jc] += wv[jr] * xv[jc];
        }
    }
    __syncthreads();
    #pragma unroll
    for (int jr = 0; jr < 4; jr++)
        #pragma unroll
        for (int jc = 0; jc < 8; jc++)
            St[(tx + 32 * jc) * 33 + ty * 4 + jr] = acc[jr][jc];
    __syncthreads();
    float* dst = outT + (long)b * 256 * 256 + r0;
    for (int i = tid; i < 32 * 256; i += 256) {
        int l = i >> 5, rr = i & 31;
        dst[l * 256 + rr] = St[l * 33 + rr];
    }
}

// ===== fused lrelu + dilated conv, D templated (R10 proven) =================
template<int D>
__global__ void __launch_bounds__(256) k_dconv(const float* __restrict__ hin,
        const float* __restrict__ w, const float* __restrict__ bias,
        float* __restrict__ out) {
    extern __shared__ float sm[];
    const int PITCH = 312;
    float* Xs = sm;                  // 32*312
    float* Ws = sm + 32 * PITCH;     // 3072
    int b = blockIdx.y;
    int t0 = blockIdx.x * 256;
    int tid = threadIdx.y * 32 + threadIdx.x;
    const int W2 = 256 + 2 * D;
    const float* hb = hin + (long)b * 32 * T_FULL;
    for (int i = tid; i < 32 * W2; i += 256) {
        int ci = i / W2, p = i - ci * W2;
        int t = t0 - D + p;
        float v = ((unsigned)t < (unsigned)T_FULL) ? hb[(long)ci * T_FULL + t] : 0.f;
        Xs[ci * PITCH + p] = lrelu(v);
    }
    for (int i = tid; i < 3072; i += 256) Ws[i] = w[i];
    __syncthreads();
    int tx = threadIdx.x, ty = threadIdx.y;   // ty in 0..7
    u64t acc2[4][4];
    #pragma unroll
    for (int jr = 0; jr < 4; jr++)
        #pragma unroll
        for (int q = 0; q < 4; q++) acc2[jr][q] = 0ull;
    for (int ci = 0; ci < 32; ci++) {
        const float* xrow = Xs + ci * PITCH + tx;
        const float* wrow = Ws + (ty * 4) * 96 + ci * 3;
        #pragma unroll
        for (int k = 0; k < 3; k++) {
            u64t x2[4];
            #pragma unroll
            for (int q = 0; q < 4; q++)
                x2[q] = pk2(xrow[64 * q + k * D], xrow[64 * q + 32 + k * D]);
            #pragma unroll
            for (int jr = 0; jr < 4; jr++) {
                float wv = wrow[jr * 96 + k];
                u64t w2 = pk2(wv, wv);
                #pragma unroll
                for (int q = 0; q < 4; q++)
                    acc2[jr][q] = ffma2(w2, x2[q], acc2[jr][q]);
            }
        }
    }
    #pragma unroll
    for (int jr = 0; jr < 4; jr++) {
        int co = ty * 4 + jr;
        float bv = bias[co];
        float* ob = out + ((long)(b * 32 + co)) * T_FULL + t0 + tx;
        #pragma unroll
        for (int q = 0; q < 4; q++) {
            float lo, hi;
            upk2(acc2[jr][q], lo, hi);
            ob[64 * q]      = lrelu(lo + bv);
            ob[64 * q + 32] = lrelu(hi + bv);
        }
    }
}

// ===== LVC: 512 threads (32x16), 2 co-pairs x 8 t per thread (R9 proven) ====
__global__ void __launch_bounds__(512) k_lvc(const float* __restrict__ y,
        const float* __restrict__ khT, const float* __restrict__ bhT,
        const float* __restrict__ res, float* __restrict__ out, int layer) {
    extern __shared__ float sm[];
    float* Ks = sm;             // 6144
    float* Xs = sm + 6144;      // 32*258
    float* Bs = Xs + 32 * 258;  // 64
    int b = blockIdx.y, l = blockIdx.x;
    int tid = threadIdx.y * 32 + threadIdx.x;
    const float* ksrc = khT + ((long)(b * 256 + l)) * KC + layer * 6144;
    for (int i = tid; i < 6144; i += 512) Ks[i] = ksrc[i];
    const float* yb = y + (long)b * 32 * T_FULL;
    int tbase = l * 256 - 1;
    for (int i = tid; i < 32 * 258; i += 512) {
        int ci = i / 258, p = i - ci * 258;
        int t = tbase + p;
        Xs[i] = ((unsigned)t < (unsigned)T_FULL) ? yb[(long)ci * T_FULL + t] : 0.f;
    }
    if (tid < 64) Bs[tid] = bhT[((long)(b * 256 + l)) * 256 + layer * 64 + tid];
    __syncthreads();
    int tx = threadIdx.x, ty = threadIdx.y;   // ty in 0..15
    u64t a2A[2][4], a2B[2][4];
    #pragma unroll
    for (int jr = 0; jr < 2; jr++) {
        int o = ty * 2 + jr;
        u64t bA = pk2(Bs[o], Bs[o]);
        u64t bB = pk2(Bs[o + 32], Bs[o + 32]);
        #pragma unroll
        for (int q = 0; q < 4; q++) { a2A[jr][q] = bA; a2B[jr][q] = bB; }
    }
    for (int ci = 0; ci < 32; ci++) {
        const float* xrow = Xs + ci * 258 + tx;
        const float* krow = Ks + ci * 192 + ty * 6;      // o*3 = ty*6 + jr*3
        #pragma unroll
        for (int k = 0; k < 3; k++) {
            u64t x2[4];
            #pragma unroll
            for (int q = 0; q < 4; q++)
                x2[q] = pk2(xrow[64 * q + k], xrow[64 * q + 32 + k]);
            #pragma unroll
            for (int jr = 0; jr < 2; jr++) {
                float wa = krow[jr * 3 + k];
                float wb = krow[96 + jr * 3 + k];        // (o+32)*3 = o*3 + 96
                u64t wA = pk2(wa, wa), wB = pk2(wb, wb);
                #pragma unroll
                for (int q = 0; q < 4; q++) {
                    a2A[jr][q] = ffma2(wA, x2[q], a2A[jr][q]);
                    a2B[jr][q] = ffma2(wB, x2[q], a2B[jr][q]);
                }
            }
        }
    }
    #pragma unroll
    for (int jr = 0; jr < 2; jr++) {
        int co = ty * 2 + jr;
        const float* rb = res + ((long)(b * 32 + co)) * T_FULL + l * 256 + tx;
        float* ob = out + ((long)(b * 32 + co)) * T_FULL + l * 256 + tx;
        #pragma unroll
        for (int q = 0; q < 4; q++) {
            float aL, aH, cL, cH;
            upk2(a2A[jr][q], aL, aH);
            upk2(a2B[jr][q], cL, cH);
            #pragma unroll
            for (int h = 0; h < 2; h++) {
                float a = h ? aH : aL;
                float c = h ? cH : cL;
                float sa = 1.f / (1.f + __expf(-a));
                float cc = fminf(fmaxf(c, -15.f), 15.f);
                float e2 = __expf(2.f * cc);
                float th = (e2 - 1.f) / (e2 + 1.f);
                int off = 64 * q + 32 * h;
                ob[off] = sa * th + rb[off];
            }
        }
    }
}

// ---- dconv dispatch (compile-time D) ----------------------------------------
static void launch_dconv(int D, const float* in, const float* w, const float* b,
                         float* out, int smem) {
    dim3 g(256, NB), t(32, 8);
    switch (D) {
        case 1:  k_dconv<1> <<<g, t, smem>>>(in, w, b, out); break;
        case 3:  k_dconv<3> <<<g, t, smem>>>(in, w, b, out); break;
        case 9:  k_dconv<9> <<<g, t, smem>>>(in, w, b, out); break;
        default: k_dconv<27><<<g, t, smem>>>(in, w, b, out); break;
    }
}

// ============================== launcher =====================================
extern "C" void kernel_launch(void* const* d_in, const int* in_sizes, int n_in,
                              void* d_out, int out_size) {
    const float* hidden  = (const float*)d_in[0];
    const float* spec    = (const float*)d_in[1];
    const float* convt_w = (const float*)d_in[2];
    const float* convt_b = (const float*)d_in[3];
    const float* kp_in_w = (const float*)d_in[4];
    const float* kp_in_b = (const float*)d_in[5];
    const float* rb_w1   = (const float*)d_in[6];
    const float* rb_b1   = (const float*)d_in[7];
    const float* rb_w2   = (const float*)d_in[8];
    const float* rb_b2   = (const float*)d_in[9];
    const float* kern_w  = (const float*)d_in[10];
    const float* kern_b  = (const float*)d_in[11];
    const float* bias_w  = (const float*)d_in[12];
    const float* bias_b  = (const float*)d_in[13];
    const float* lvc_w   = (const float*)d_in[14];
    const float* lvc_b   = (const float*)d_in[15];
    float* out = (float*)d_out;

    float *hA, *hB, *yb, *kp0, *khT, *bhT;
    cudaGetSymbolAddress((void**)&hA,  g_hA);
    cudaGetSymbolAddress((void**)&hB,  g_hB);
    cudaGetSymbolAddress((void**)&yb,  g_y);
    cudaGetSymbolAddress((void**)&kp0, g_kp0);
    cudaGetSymbolAddress((void**)&khT, g_kh);
    cudaGetSymbolAddress((void**)&bhT, g_bh);

    const int SMEM_KERN = (64*258 + 192*64) * 4;     // 115200 (St aliased)
    const int SMEM_BG   = (64*258 + 32*192) * 4;     // 90624
    const int SMEM_DC   = (32*312 + 3072) * 4;       // 52224
    const int SMEM_LVC  = (6144 + 32*258 + 64) * 4;  // 57856
    cudaFuncSetAttribute(k_kern,  cudaFuncAttributeMaxDynamicSharedMemorySize, SMEM_KERN);
    cudaFuncSetAttribute(k_biasg, cudaFuncAttributeMaxDynamicSharedMemorySize, SMEM_BG);
    cudaFuncSetAttribute(k_dconv<1>,  cudaFuncAttributeMaxDynamicSharedMemorySize, SMEM_DC);
    cudaFuncSetAttribute(k_dconv<3>,  cudaFuncAttributeMaxDynamicSharedMemorySize, SMEM_DC);
    cudaFuncSetAttribute(k_dconv<9>,  cudaFuncAttributeMaxDynamicSharedMemorySize, SMEM_DC);
    cudaFuncSetAttribute(k_dconv<27>, cudaFuncAttributeMaxDynamicSharedMemorySize, SMEM_DC);
    cudaFuncSetAttribute(k_lvc,   cudaFuncAttributeMaxDynamicSharedMemorySize, SMEM_LVC);

    // #1..#2
    k_convt<<<(NB*CH*8192)/256, 256>>>(hidden, convt_w, convt_b, hA);
    k_kpf<<<dim3(16, NB), 256>>>(spec, kp_in_w, kp_in_b, rb_w1, rb_b1, rb_w2, rb_b2, kp0);
    // #3: dconv layer 0 (needs only hA)
    launch_dconv(1, hA, lvc_w, lvc_b, yb, SMEM_DC);
    // #4: kern conv (profiled slot)
    k_kern<<<dim3(KC/64, NB), dim3(32, 16), SMEM_KERN>>>(kp0, kern_w, kern_b, khT);
    // #5: bias conv
    k_biasg<<<dim3(8, NB), dim3(32, 8), SMEM_BG>>>(kp0, bias_w, bias_b, bhT);
    // #6: lvc layer 0
    k_lvc<<<dim3(256, NB), dim3(32, 16), SMEM_LVC>>>(yb, khT, bhT, hA, hB, 0);

    const int DIL[4] = {1, 3, 9, 27};
    const float* cur = hB;
    for (int i = 1; i < 4; i++) {
        launch_dconv(DIL[i], cur, lvc_w + i*3072, lvc_b + i*32, yb, SMEM_DC);
        float* nxt = (i == 3) ? out : ((i & 1) ? hA : hB);
        k_lvc<<<dim3(256, NB), dim3(32, 16), SMEM_LVC>>>(yb, khT, bhT, cur, nxt, i);
        cur = nxt;
    }
}

// round 15
// speedup vs baseline: 1.0150x; 1.0150x over previous
#include <cuda_runtime.h>
#include <math.h>

#define T_FULL 65536
#define NB 4
#define CH 32
#define LL 256
#define HH 64
#define KC 24576

// -------- scratch (static device allocations; allowed) --------
__device__ float g_hA[NB*CH*T_FULL];
__device__ float g_hB[NB*CH*T_FULL];
__device__ float g_kp0[NB*HH*LL];
__device__ float g_kh[NB*LL*KC];     // transposed: [b][l][kc]
__device__ float g_bh[NB*LL*256];    // transposed: [b][l][bc]

__device__ __forceinline__ float lrelu(float v) { return v >= 0.f ? v : 0.2f * v; }

// ---- packed f32x2 helpers (SASS FFMA2; IEEE-identical to 2x fmaf) ----------
typedef unsigned long long u64t;
__device__ __forceinline__ u64t pk2(float lo, float hi) {
    u64t r; asm("mov.b64 %0, {%1, %2};" : "=l"(r) : "f"(lo), "f"(hi)); return r;
}
__device__ __forceinline__ u64t ffma2(u64t a, u64t b, u64t c) {
    u64t d; asm("fma.rn.f32x2 %0, %1, %2, %3;" : "=l"(d) : "l"(a), "l"(b), "l"(c));
    return d;
}
__device__ __forceinline__ void upk2(u64t v, float& lo, float& hi) {
    asm("mov.b64 {%0, %1}, %2;" : "=f"(lo), "=f"(hi) : "l"(v));
}

// ======== conv_transpose1d (stride 8, k=16, pad 4): 8 outputs/thread ========
__global__ void __launch_bounds__(256) k_convt(const float* __restrict__ x,
        const float* __restrict__ w, const float* __restrict__ bias,
        float* __restrict__ out) {
    int gid = blockIdx.x * 256 + threadIdx.x;
    int tg = gid & 8191;
    int o  = (gid >> 13) & 31;
    int b  = gid >> 18;
    float acc[8];
    float bv = bias[o];
    #pragma unroll
    for (int j = 0; j < 8; j++) acc[j] = bv;
    const float* xb = x + (b * CH) * 8192;
    bool hm = (tg > 0), hp = (tg < 8191);
    #pragma unroll
    for (int i = 0; i < 32; i++) {
        const float* xr = xb + i * 8192 + tg;
        float x0 = xr[0];
        float xm = hm ? xr[-1] : 0.f;
        float xp = hp ? xr[1]  : 0.f;
        const float* wr = w + (i * 32 + o) * 16;
        #pragma unroll
        for (int j = 0; j < 4; j++)
            acc[j] = fmaf(x0, wr[j + 4], fmaf(xm, wr[j + 12], acc[j]));
        #pragma unroll
        for (int j = 4; j < 8; j++)
            acc[j] = fmaf(xp, wr[j - 4], fmaf(x0, wr[j + 4], acc[j]));
    }
    float4* dst = (float4*)(out + ((long)(b * 32 + o)) * T_FULL + tg * 8);
    dst[0] = make_float4(acc[0], acc[1], acc[2], acc[3]);
    dst[1] = make_float4(acc[4], acc[5], acc[6], acc[7]);
}

// ======== fused kernel-predictor front end: in-conv + 3 residual blocks ======
__global__ void __launch_bounds__(256) k_kpf(const float* __restrict__ spec,
        const float* __restrict__ kin_w, const float* __restrict__ kin_b,
        const float* __restrict__ w1, const float* __restrict__ b1,
        const float* __restrict__ w2, const float* __restrict__ b2,
        float* __restrict__ out) {
    __shared__ float S[100 * 37];
    __shared__ float A[64 * 36];
    __shared__ float Bm[64 * 36];
    int b = blockIdx.y;
    int lbase = blockIdx.x * 16 - 8;
    int tid = threadIdx.x;
    for (int i = tid; i < 100 * 37; i += 256) S[i] = 0.f;
    for (int i = tid; i < 64 * 36; i += 256) { A[i] = 0.f; Bm[i] = 0.f; }
    __syncthreads();
    for (int i = tid; i < 100 * 32; i += 256) {
        int c = i >> 5, p = i & 31;
        int l = lbase + p;
        if ((unsigned)l < 256u) S[c * 37 + p + 2] = spec[(b * 100 + c) * 256 + l];
    }
    __syncthreads();
    int o = tid >> 2, pq = tid & 3;
    float acc[8];
    {
        float bv = kin_b[o];
        #pragma unroll
        for (int j = 0; j < 8; j++) acc[j] = bv;
        for (int c = 0; c < 100; c++) {
            const float* wr = kin_w + (o * 100 + c) * 5;
            const float* sr = S + c * 37;
            #pragma unroll
            for (int k = 0; k < 5; k++) {
                float wv = wr[k];
                #pragma unroll
                for (int j = 0; j < 8; j++) acc[j] += sr[pq + 4 * j + k] * wv;
            }
        }
        #pragma unroll
        for (int j = 0; j < 8; j++) {
            int p = pq + 4 * j, l = lbase + p;
            A[o * 36 + p + 1] = ((unsigned)l < 256u) ? acc[j] : 0.f;
        }
    }
    __syncthreads();
    for (int it = 0; it < 3; it++) {
        {
            float bv = b1[it * 64 + o];
            #pragma unroll
            for (int j = 0; j < 8; j++) acc[j] = bv;
            const float* wbase = w1 + it * 64 * 64 * 3 + o * 64 * 3;
            for (int c = 0; c < 64; c++) {
                const float* wr = wbase + c * 3;
                const float* ar = A + c * 36;
                #pragma unroll
                for (int k = 0; k < 3; k++) {
                    float wv = wr[k];
                    #pragma unroll
                    for (int j = 0; j < 8; j++) acc[j] += ar[pq + 4 * j + k] * wv;
                }
            }
            #pragma unroll
            for (int j = 0; j < 8; j++) {
                int p = pq + 4 * j, l = lbase + p;
                Bm[o * 36 + p + 1] = ((unsigned)l < 256u) ? lrelu(acc[j]) : 0.f;
            }
        }
        __syncthreads();
        {
            float bv = b2[it * 64 + o];
            #pragma unroll
            for (int j = 0; j < 8; j++) acc[j] = bv;
            const float* wbase = w2 + it * 64 * 64 * 3 + o * 64 * 3;
            for (int c = 0; c < 64; c++) {
                const float* wr = wbase + c * 3;
                const float* br = Bm + c * 36;
                #pragma unroll
                for (int k = 0; k < 3; k++) {
                    float wv = wr[k];
                    #pragma unroll
                    for (int j = 0; j < 8; j++) acc[j] += br[pq + 4 * j + k] * wv;
                }
            }
            #pragma unroll
            for (int j = 0; j < 8; j++) {
                int p = pq + 4 * j, l = lbase + p;
                float v = lrelu(acc[j]) + A[o * 36 + p + 1];
                A[o * 36 + p + 1] = ((unsigned)l < 256u) ? v : 0.f;
            }
        }
        __syncthreads();
    }
    #pragma unroll
    for (int j = 0; j < 8; j++) {
        int p = pq + 4 * j;
        if (p >= 8 && p < 24)
            out[(b * 64 + o) * 256 + lbase + p] = A[o * 36 + p + 1];
    }
}

// ===== kern conv (R11 proven form, 233us): 512 threads, scalar weights ======
__global__ void __launch_bounds__(512, 2) k_kern(const float* __restrict__ h,
        const float* __restrict__ w, const float* __restrict__ bias,
        float* __restrict__ outT) {
    extern __shared__ float sm[];
    float* Xs = sm;                    // 64*258
    float* Ws = sm + 64 * 258;         // 64*192
    float* St = sm;                    // 256*65 (aliased)
    int b = blockIdx.y;
    int r0 = blockIdx.x * 64;
    int tid = threadIdx.y * 32 + threadIdx.x;
    const float* hb = h + b * 64 * 256;
    for (int i = tid; i < 64 * 258; i += 512) {
        int ci = i / 258, p = i - ci * 258;
        int lp = p - 1;
        Xs[i] = ((unsigned)lp < 256u) ? hb[ci * 256 + lp] : 0.f;
    }
    const float* wsrc = w + (long)r0 * 192;
    for (int i = tid; i < 64 * 192; i += 512) Ws[i] = wsrc[i];
    __syncthreads();
    int tx = threadIdx.x, ty = threadIdx.y;   // ty in 0..15
    u64t acc2[4][4];
    #pragma unroll
    for (int jr = 0; jr < 4; jr++) {
        float bv = bias[r0 + ty * 4 + jr];
        u64t bp = pk2(bv, bv);
        #pragma unroll
        for (int q = 0; q < 4; q++) acc2[jr][q] = bp;
    }
    for (int ci = 0; ci < 64; ci++) {
        const float* xrow = Xs + ci * 258 + tx;
        const float* wcol = Ws + ty * 4 * 192 + ci * 3;
        #pragma unroll
        for (int k = 0; k < 3; k++) {
            u64t x2[4];
            #pragma unroll
            for (int q = 0; q < 4; q++)
                x2[q] = pk2(xrow[64 * q + k], xrow[64 * q + 32 + k]);
            #pragma unroll
            for (int jr = 0; jr < 4; jr++) {
                float wv = wcol[jr * 192 + k];
                u64t w2 = pk2(wv, wv);
                #pragma unroll
                for (int q = 0; q < 4; q++)
                    acc2[jr][q] = ffma2(w2, x2[q], acc2[jr][q]);
            }
        }
    }
    __syncthreads();
    #pragma unroll
    for (int jr = 0; jr < 4; jr++)
        #pragma unroll
        for (int q = 0; q < 4; q++) {
            float lo, hi;
            upk2(acc2[jr][q], lo, hi);
            St[(tx + 64 * q) * 65 + ty * 4 + jr] = lo;
            St[(tx + 64 * q + 32) * 65 + ty * 4 + jr] = hi;
        }
    __syncthreads();
    float* dst = outT + (long)b * 256 * KC + r0;
    for (int i = tid; i < 64 * 256; i += 512) {
        int l = i >> 6, kc = i & 63;
        dst[(long)l * KC + kc] = St[l * 65 + kc];
    }
}

// ===== bias conv as tiled GEMM (unchanged, proven) ==========================
__global__ void __launch_bounds__(256) k_biasg(const float* __restrict__ h,
        const float* __restrict__ w, const float* __restrict__ bias,
        float* __restrict__ outT) {
    extern __shared__ float sm[];
    float* Xs = sm;                    // 64*258
    float* Ws = sm + 64 * 258;         // 32*192
    float* St = sm;                    // 256*33 (aliased)
    int b = blockIdx.y;
    int r0 = blockIdx.x * 32;
    int tid = threadIdx.y * 32 + threadIdx.x;
    const float* hb = h + b * 64 * 256;
    for (int i = tid; i < 64 * 258; i += 256) {
        int ci = i / 258, p = i - ci * 258;
        int lp = p - 1;
        Xs[i] = ((unsigned)lp < 256u) ? hb[ci * 256 + lp] : 0.f;
    }
    const float* wsrc = w + (long)r0 * 192;
    for (int i = tid; i < 32 * 192; i += 256) Ws[i] = wsrc[i];
    __syncthreads();
    int tx = threadIdx.x, ty = threadIdx.y;
    float acc[4][8];
    #pragma unroll
    for (int jr = 0; jr < 4; jr++) {
        float bv = bias[r0 + ty * 4 + jr];
        #pragma unroll
        for (int jc = 0; jc < 8; jc++) acc[jr][jc] = bv;
    }
    for (int ci = 0; ci < 64; ci++) {
        const float* xrow = Xs + ci * 258 + tx;
        const float* wcol = Ws + ty * 4 * 192 + ci * 3;
        #pragma unroll
        for (int k = 0; k < 3; k++) {
            float xv[8], wv[4];
            #pragma unroll
            for (int jc = 0; jc < 8; jc++) xv[jc] = xrow[32 * jc + k];
            #pragma unroll
            for (int jr = 0; jr < 4; jr++) wv[jr] = wcol[jr * 192 + k];
            #pragma unroll
            for (int jr = 0; jr < 4; jr++)
                #pragma unroll
                for (int jc = 0; jc < 8; jc++)
                    acc[jr][jc] += wv[jr] * xv[jc];
        }
    }
    __syncthreads();
    #pragma unroll
    for (int jr = 0; jr < 4; jr++)
        #pragma unroll
        for (int jc = 0; jc < 8; jc++)
            St[(tx + 32 * jc) * 33 + ty * 4 + jr] = acc[jr][jc];
    __syncthreads();
    float* dst = outT + (long)b * 256 * 256 + r0;
    for (int i = tid; i < 32 * 256; i += 256) {
        int l = i >> 5, rr = i & 31;
        dst[l * 256 + rr] = St[l * 33 + rr];
    }
}

// ===== FUSED dilated-conv + LVC + gate + residual, per (b,l) tile ===========
// Stage 1: dconv for 258 positions (t = l*256-1 .. l*256+256) directly into
// smem Xs (the buffer lvc reads). Stage 2: R9 lvc mainloop verbatim.
// Ks aliases the stage-1 input buffer (loaded after stage-1 compute).
// Accumulation orders identical to the separate kernels -> bit-identical.
template<int D>
__global__ void __launch_bounds__(512, 2) k_dlvc(const float* __restrict__ hin,
        const float* __restrict__ dw, const float* __restrict__ dbias,
        const float* __restrict__ khT, const float* __restrict__ bhT,
        float* __restrict__ out, int layer) {
    const int W3 = 258 + 2 * D;          // valid input window
    const int PITCHX = 288 + 2 * D;      // padded so p up to 287 reads stay in-bounds
    extern __shared__ float sm[];
    float* Ws  = sm;                      // 3072
    float* Xs  = sm + 3072;               // 32*258 = 8256
    float* Bs  = sm + 3072 + 8256;        // 64
    float* Xin = sm + 3072 + 8256 + 64;   // 32*PITCHX  (aliased by Ks later)
    float* Ks  = Xin;                     // 6144 (after stage 1)
    int b = blockIdx.y, l = blockIdx.x;
    int tid = threadIdx.y * 32 + threadIdx.x;
    int tx = threadIdx.x, ty = threadIdx.y;   // ty in 0..15

    // loads: dconv weights, lvc bias, lrelu'd input window
    for (int i = tid; i < 3072; i += 512) Ws[i] = dw[i];
    if (tid < 64) Bs[tid] = bhT[((long)(b * 256 + l)) * 256 + layer * 64 + tid];
    const float* hb = hin + (long)b * 32 * T_FULL;
    int tstart = l * 256 - 1 - D;
    for (int i = tid; i < 32 * W3; i += 512) {
        int ci = i / W3, u = i - ci * W3;
        int t = tstart + u;
        float v = ((unsigned)t < (unsigned)T_FULL) ? hb[(long)ci * T_FULL + t] : 0.f;
        Xin[ci * PITCHX + u] = lrelu(v);
    }
    __syncthreads();

    // ---- stage 1: dilated conv, 2 channels x 9 positions per thread --------
    {
        float acc1[2][9];
        #pragma unroll
        for (int jr = 0; jr < 2; jr++)
            #pragma unroll
            for (int j = 0; j < 9; j++) acc1[jr][j] = 0.f;
        for (int ci = 0; ci < 32; ci++) {
            const float* xr = Xin + ci * PITCHX + tx;
            const float* w0 = Ws + (ty * 2) * 96 + ci * 3;
            #pragma unroll
            for (int k = 0; k < 3; k++) {
                float wv0 = w0[k];
                float wv1 = w0[96 + k];
                #pragma unroll
                for (int j = 0; j < 9; j++) {
                    float xv = xr[32 * j + k * D];   // p=tx+32j reads u=p+kD (padded)
                    acc1[0][j] = fmaf(wv0, xv, acc1[0][j]);
                    acc1[1][j] = fmaf(wv1, xv, acc1[1][j]);
                }
            }
        }
        __syncthreads();   // all Xin reads done before Ks overwrites it
        // Ks load (aliases Xin)
        const float* ksrc = khT + ((long)(b * 256 + l)) * KC + layer * 6144;
        for (int i = tid; i < 6144; i += 512) Ks[i] = ksrc[i];
        // write stage-1 results into Xs
        #pragma unroll
        for (int jr = 0; jr < 2; jr++) {
            int co = ty * 2 + jr;
            float bv = dbias[co];
            #pragma unroll
            for (int j = 0; j < 9; j++) {
                int p = tx + 32 * j;
                if (p < 258) Xs[co * 258 + p] = lrelu(acc1[jr][j] + bv);
            }
        }
    }
    __syncthreads();

    // ---- stage 2: LVC mainloop (R9 form) -----------------------------------
    u64t a2A[2][4], a2B[2][4];
    #pragma unroll
    for (int jr = 0; jr < 2; jr++) {
        int o = ty * 2 + jr;
        u64t bA = pk2(Bs[o], Bs[o]);
        u64t bB = pk2(Bs[o + 32], Bs[o + 32]);
        #pragma unroll
        for (int q = 0; q < 4; q++) { a2A[jr][q] = bA; a2B[jr][q] = bB; }
    }
    for (int ci = 0; ci < 32; ci++) {
        const float* xrow = Xs + ci * 258 + tx;
        const float* krow = Ks + ci * 192 + ty * 6;
        #pragma unroll
        for (int k = 0; k < 3; k++) {
            u64t x2[4];
            #pragma unroll
            for (int q = 0; q < 4; q++)
                x2[q] = pk2(xrow[64 * q + k], xrow[64 * q + 32 + k]);
            #pragma unroll
            for (int jr = 0; jr < 2; jr++) {
                float wa = krow[jr * 3 + k];
                float wb = krow[96 + jr * 3 + k];
                u64t wA = pk2(wa, wa), wB = pk2(wb, wb);
                #pragma unroll
                for (int q = 0; q < 4; q++) {
                    a2A[jr][q] = ffma2(wA, x2[q], a2A[jr][q]);
                    a2B[jr][q] = ffma2(wB, x2[q], a2B[jr][q]);
                }
            }
        }
    }
    #pragma unroll
    for (int jr = 0; jr < 2; jr++) {
        int co = ty * 2 + jr;
        const float* rb = hin + ((long)(b * 32 + co)) * T_FULL + l * 256 + tx;
        float* ob = out + ((long)(b * 32 + co)) * T_FULL + l * 256 + tx;
        #pragma unroll
        for (int q = 0; q < 4; q++) {
            float aL, aH, cL, cH;
            upk2(a2A[jr][q], aL, aH);
            upk2(a2B[jr][q], cL, cH);
            #pragma unroll
            for (int h = 0; h < 2; h++) {
                float a = h ? aH : aL;
                float c = h ? cH : cL;
                float sa = 1.f / (1.f + __expf(-a));
                float cc = fminf(fmaxf(c, -15.f), 15.f);
                float e2 = __expf(2.f * cc);
                float th = (e2 - 1.f) / (e2 + 1.f);
                int off = 64 * q + 32 * h;
                ob[off] = sa * th + rb[off];
            }
        }
    }
}

// ---- fused dispatch ---------------------------------------------------------
static int dlvc_smem(int D) { return (3072 + 8256 + 64 + 32 * (288 + 2 * D)) * 4; }
static void launch_dlvc(int D, const float* hin, const float* dw, const float* db,
                        const float* khT, const float* bhT, float* out, int layer) {
    dim3 g(256, NB), t(32, 16);
    int smem = dlvc_smem(D);
    switch (D) {
        case 1:  k_dlvc<1> <<<g, t, smem>>>(hin, dw, db, khT, bhT, out, layer); break;
        case 3:  k_dlvc<3> <<<g, t, smem>>>(hin, dw, db, khT, bhT, out, layer); break;
        case 9:  k_dlvc<9> <<<g, t, smem>>>(hin, dw, db, khT, bhT, out, layer); break;
        default: k_dlvc<27><<<g, t, smem>>>(hin, dw, db, khT, bhT, out, layer); break;
    }
}

// ============================== launcher =====================================
extern "C" void kernel_launch(void* const* d_in, const int* in_sizes, int n_in,
                              void* d_out, int out_size) {
    const float* hidden  = (const float*)d_in[0];
    const float* spec    = (const float*)d_in[1];
    const float* convt_w = (const float*)d_in[2];
    const float* convt_b = (const float*)d_in[3];
    const float* kp_in_w = (const float*)d_in[4];
    const float* kp_in_b = (const float*)d_in[5];
    const float* rb_w1   = (const float*)d_in[6];
    const float* rb_b1   = (const float*)d_in[7];
    const float* rb_w2   = (const float*)d_in[8];
    const float* rb_b2   = (const float*)d_in[9];
    const float* kern_w  = (const float*)d_in[10];
    const float* kern_b  = (const float*)d_in[11];
    const float* bias_w  = (const float*)d_in[12];
    const float* bias_b  = (const float*)d_in[13];
    const float* lvc_w   = (const float*)d_in[14];
    const float* lvc_b   = (const float*)d_in[15];
    float* out = (float*)d_out;

    float *hA, *hB, *kp0, *khT, *bhT;
    cudaGetSymbolAddress((void**)&hA,  g_hA);
    cudaGetSymbolAddress((void**)&hB,  g_hB);
    cudaGetSymbolAddress((void**)&kp0, g_kp0);
    cudaGetSymbolAddress((void**)&khT, g_kh);
    cudaGetSymbolAddress((void**)&bhT, g_bh);

    const int SMEM_KERN = (64*258 + 64*192) * 4;     // 115200 (St aliased)
    const int SMEM_BG   = (64*258 + 32*192) * 4;     // 90624
    cudaFuncSetAttribute(k_kern,  cudaFuncAttributeMaxDynamicSharedMemorySize, SMEM_KERN);
    cudaFuncSetAttribute(k_biasg, cudaFuncAttributeMaxDynamicSharedMemorySize, SMEM_BG);
    cudaFuncSetAttribute(k_dlvc<1>,  cudaFuncAttributeMaxDynamicSharedMemorySize, dlvc_smem(1));
    cudaFuncSetAttribute(k_dlvc<3>,  cudaFuncAttributeMaxDynamicSharedMemorySize, dlvc_smem(3));
    cudaFuncSetAttribute(k_dlvc<9>,  cudaFuncAttributeMaxDynamicSharedMemorySize, dlvc_smem(9));
    cudaFuncSetAttribute(k_dlvc<27>, cudaFuncAttributeMaxDynamicSharedMemorySize, dlvc_smem(27));

    // #1..#4 (capture slot #4 = k_kern, known baseline)
    k_convt<<<(NB*CH*8192)/256, 256>>>(hidden, convt_w, convt_b, hA);
    k_kpf<<<dim3(16, NB), 256>>>(spec, kp_in_w, kp_in_b, rb_w1, rb_b1, rb_w2, rb_b2, kp0);
    k_biasg<<<dim3(8, NB), dim3(32, 8), SMEM_BG>>>(kp0, bias_w, bias_b, bhT);
    k_kern<<<dim3(KC/64, NB), dim3(32, 16), SMEM_KERN>>>(kp0, kern_w, kern_b, khT);

    // #5..#8: fused dconv+lvc per layer
    const int DIL[4] = {1, 3, 9, 27};
    const float* cur = hA;
    for (int i = 0; i < 4; i++) {
        float* nxt = (i == 3) ? out : ((i & 1) ? hA : hB);
        launch_dlvc(DIL[i], cur, lvc_w + i*3072, lvc_b + i*32, khT, bhT, nxt, i);
        cur = nxt;
    }
}

// round 16
// speedup vs baseline: 1.1223x; 1.1056x over previous
#include <cuda_runtime.h>
#include <math.h>

#define T_FULL 65536
#define NB 4
#define CH 32
#define LL 256
#define HH 64
#define KC 24576

// -------- scratch (static device allocations; allowed) --------
__device__ float g_hA[NB*CH*T_FULL];
__device__ float g_hB[NB*CH*T_FULL];
__device__ float g_y [NB*CH*T_FULL];
__device__ float g_kp0[NB*HH*LL];
__device__ float g_kh[NB*LL*KC];     // transposed: [b][l][kc]
__device__ float g_bh[NB*LL*256];    // transposed: [b][l][bc]

__device__ __forceinline__ float lrelu(float v) { return v >= 0.f ? v : 0.2f * v; }

// ---- packed f32x2 helpers (SASS FFMA2; IEEE-identical to 2x fmaf) ----------
typedef unsigned long long u64t;
__device__ __forceinline__ u64t pk2(float lo, float hi) {
    u64t r; asm("mov.b64 %0, {%1, %2};" : "=l"(r) : "f"(lo), "f"(hi)); return r;
}
__device__ __forceinline__ u64t ffma2(u64t a, u64t b, u64t c) {
    u64t d; asm("fma.rn.f32x2 %0, %1, %2, %3;" : "=l"(d) : "l"(a), "l"(b), "l"(c));
    return d;
}
__device__ __forceinline__ void upk2(u64t v, float& lo, float& hi) {
    asm("mov.b64 {%0, %1}, %2;" : "=f"(lo), "=f"(hi) : "l"(v));
}
// HW tanh (MUFU.TANH, sm_75+): 1 MUFU, saturating, abs err ~2^-11.
__device__ __forceinline__ float tanh_ap(float x) {
    float y; asm("tanh.approx.f32 %0, %1;" : "=f"(y) : "f"(x)); return y;
}

// ======== conv_transpose1d (stride 8, k=16, pad 4): 8 outputs/thread ========
__global__ void __launch_bounds__(256) k_convt(const float* __restrict__ x,
        const float* __restrict__ w, const float* __restrict__ bias,
        float* __restrict__ out) {
    int gid = blockIdx.x * 256 + threadIdx.x;
    int tg = gid & 8191;
    int o  = (gid >> 13) & 31;
    int b  = gid >> 18;
    float acc[8];
    float bv = bias[o];
    #pragma unroll
    for (int j = 0; j < 8; j++) acc[j] = bv;
    const float* xb = x + (b * CH) * 8192;
    bool hm = (tg > 0), hp = (tg < 8191);
    #pragma unroll
    for (int i = 0; i < 32; i++) {
        const float* xr = xb + i * 8192 + tg;
        float x0 = xr[0];
        float xm = hm ? xr[-1] : 0.f;
        float xp = hp ? xr[1]  : 0.f;
        const float* wr = w + (i * 32 + o) * 16;
        #pragma unroll
        for (int j = 0; j < 4; j++)
            acc[j] = fmaf(x0, wr[j + 4], fmaf(xm, wr[j + 12], acc[j]));
        #pragma unroll
        for (int j = 4; j < 8; j++)
            acc[j] = fmaf(xp, wr[j - 4], fmaf(x0, wr[j + 4], acc[j]));
    }
    float4* dst = (float4*)(out + ((long)(b * 32 + o)) * T_FULL + tg * 8);
    dst[0] = make_float4(acc[0], acc[1], acc[2], acc[3]);
    dst[1] = make_float4(acc[4], acc[5], acc[6], acc[7]);
}

// ======== fused kernel-predictor front end: in-conv + 3 residual blocks ======
__global__ void __launch_bounds__(256) k_kpf(const float* __restrict__ spec,
        const float* __restrict__ kin_w, const float* __restrict__ kin_b,
        const float* __restrict__ w1, const float* __restrict__ b1,
        const float* __restrict__ w2, const float* __restrict__ b2,
        float* __restrict__ out) {
    __shared__ float S[100 * 37];
    __shared__ float A[64 * 36];
    __shared__ float Bm[64 * 36];
    int b = blockIdx.y;
    int lbase = blockIdx.x * 16 - 8;
    int tid = threadIdx.x;
    for (int i = tid; i < 100 * 37; i += 256) S[i] = 0.f;
    for (int i = tid; i < 64 * 36; i += 256) { A[i] = 0.f; Bm[i] = 0.f; }
    __syncthreads();
    for (int i = tid; i < 100 * 32; i += 256) {
        int c = i >> 5, p = i & 31;
        int l = lbase + p;
        if ((unsigned)l < 256u) S[c * 37 + p + 2] = spec[(b * 100 + c) * 256 + l];
    }
    __syncthreads();
    int o = tid >> 2, pq = tid & 3;
    float acc[8];
    {
        float bv = kin_b[o];
        #pragma unroll
        for (int j = 0; j < 8; j++) acc[j] = bv;
        for (int c = 0; c < 100; c++) {
            const float* wr = kin_w + (o * 100 + c) * 5;
            const float* sr = S + c * 37;
            #pragma unroll
            for (int k = 0; k < 5; k++) {
                float wv = wr[k];
                #pragma unroll
                for (int j = 0; j < 8; j++) acc[j] += sr[pq + 4 * j + k] * wv;
            }
        }
        #pragma unroll
        for (int j = 0; j < 8; j++) {
            int p = pq + 4 * j, l = lbase + p;
            A[o * 36 + p + 1] = ((unsigned)l < 256u) ? acc[j] : 0.f;
        }
    }
    __syncthreads();
    for (int it = 0; it < 3; it++) {
        {
            float bv = b1[it * 64 + o];
            #pragma unroll
            for (int j = 0; j < 8; j++) acc[j] = bv;
            const float* wbase = w1 + it * 64 * 64 * 3 + o * 64 * 3;
            for (int c = 0; c < 64; c++) {
                const float* wr = wbase + c * 3;
                const float* ar = A + c * 36;
                #pragma unroll
                for (int k = 0; k < 3; k++) {
                    float wv = wr[k];
                    #pragma unroll
                    for (int j = 0; j < 8; j++) acc[j] += ar[pq + 4 * j + k] * wv;
                }
            }
            #pragma unroll
            for (int j = 0; j < 8; j++) {
                int p = pq + 4 * j, l = lbase + p;
                Bm[o * 36 + p + 1] = ((unsigned)l < 256u) ? lrelu(acc[j]) : 0.f;
            }
        }
        __syncthreads();
        {
            float bv = b2[it * 64 + o];
            #pragma unroll
            for (int j = 0; j < 8; j++) acc[j] = bv;
            const float* wbase = w2 + it * 64 * 64 * 3 + o * 64 * 3;
            for (int c = 0; c < 64; c++) {
                const float* wr = wbase + c * 3;
                const float* br = Bm + c * 36;
                #pragma unroll
                for (int k = 0; k < 3; k++) {
                    float wv = wr[k];
                    #pragma unroll
                    for (int j = 0; j < 8; j++) acc[j] += br[pq + 4 * j + k] * wv;
                }
            }
            #pragma unroll
            for (int j = 0; j < 8; j++) {
                int p = pq + 4 * j, l = lbase + p;
                float v = lrelu(acc[j]) + A[o * 36 + p + 1];
                A[o * 36 + p + 1] = ((unsigned)l < 256u) ? v : 0.f;
            }
        }
        __syncthreads();
    }
    #pragma unroll
    for (int j = 0; j < 8; j++) {
        int p = pq + 4 * j;
        if (p >= 8 && p < 24)
            out[(b * 64 + o) * 256 + lbase + p] = A[o * 36 + p + 1];
    }
}

// ===== kern conv (R11 proven form): 512 threads, scalar weights =============
__global__ void __launch_bounds__(512, 2) k_kern(const float* __restrict__ h,
        const float* __restrict__ w, const float* __restrict__ bias,
        float* __restrict__ outT) {
    extern __shared__ float sm[];
    float* Xs = sm;                    // 64*258
    float* Ws = sm + 64 * 258;         // 64*192
    float* St = sm;                    // 256*65 (aliased)
    int b = blockIdx.y;
    int r0 = blockIdx.x * 64;
    int tid = threadIdx.y * 32 + threadIdx.x;
    const float* hb = h + b * 64 * 256;
    for (int i = tid; i < 64 * 258; i += 512) {
        int ci = i / 258, p = i - ci * 258;
        int lp = p - 1;
        Xs[i] = ((unsigned)lp < 256u) ? hb[ci * 256 + lp] : 0.f;
    }
    const float* wsrc = w + (long)r0 * 192;
    for (int i = tid; i < 64 * 192; i += 512) Ws[i] = wsrc[i];
    __syncthreads();
    int tx = threadIdx.x, ty = threadIdx.y;   // ty in 0..15
    u64t acc2[4][4];
    #pragma unroll
    for (int jr = 0; jr < 4; jr++) {
        float bv = bias[r0 + ty * 4 + jr];
        u64t bp = pk2(bv, bv);
        #pragma unroll
        for (int q = 0; q < 4; q++) acc2[jr][q] = bp;
    }
    for (int ci = 0; ci < 64; ci++) {
        const float* xrow = Xs + ci * 258 + tx;
        const float* wcol = Ws + ty * 4 * 192 + ci * 3;
        #pragma unroll
        for (int k = 0; k < 3; k++) {
            u64t x2[4];
            #pragma unroll
            for (int q = 0; q < 4; q++)
                x2[q] = pk2(xrow[64 * q + k], xrow[64 * q + 32 + k]);
            #pragma unroll
            for (int jr = 0; jr < 4; jr++) {
                float wv = wcol[jr * 192 + k];
                u64t w2 = pk2(wv, wv);
                #pragma unroll
                for (int q = 0; q < 4; q++)
                    acc2[jr][q] = ffma2(w2, x2[q], acc2[jr][q]);
            }
        }
    }
    __syncthreads();
    #pragma unroll
    for (int jr = 0; jr < 4; jr++)
        #pragma unroll
        for (int q = 0; q < 4; q++) {
            float lo, hi;
            upk2(acc2[jr][q], lo, hi);
            St[(tx + 64 * q) * 65 + ty * 4 + jr] = lo;
            St[(tx + 64 * q + 32) * 65 + ty * 4 + jr] = hi;
        }
    __syncthreads();
    float* dst = outT + (long)b * 256 * KC + r0;
    for (int i = tid; i < 64 * 256; i += 512) {
        int l = i >> 6, kc = i & 63;
        dst[(long)l * KC + kc] = St[l * 65 + kc];
    }
}

// ===== bias conv as tiled GEMM (unchanged, proven) ==========================
__global__ void __launch_bounds__(256) k_biasg(const float* __restrict__ h,
        const float* __restrict__ w, const float* __restrict__ bias,
        float* __restrict__ outT) {
    extern __shared__ float sm[];
    float* Xs = sm;                    // 64*258
    float* Ws = sm + 64 * 258;         // 32*192
    float* St = sm;                    // 256*33 (aliased)
    int b = blockIdx.y;
    int r0 = blockIdx.x * 32;
    int tid = threadIdx.y * 32 + threadIdx.x;
    const float* hb = h + b * 64 * 256;
    for (int i = tid; i < 64 * 258; i += 256) {
        int ci = i / 258, p = i - ci * 258;
        int lp = p - 1;
        Xs[i] = ((unsigned)lp < 256u) ? hb[ci * 256 + lp] : 0.f;
    }
    const float* wsrc = w + (long)r0 * 192;
    for (int i = tid; i < 32 * 192; i += 256) Ws[i] = wsrc[i];
    __syncthreads();
    int tx = threadIdx.x, ty = threadIdx.y;
    float acc[4][8];
    #pragma unroll
    for (int jr = 0; jr < 4; jr++) {
        float bv = bias[r0 + ty * 4 + jr];
        #pragma unroll
        for (int jc = 0; jc < 8; jc++) acc[jr][jc] = bv;
    }
    for (int ci = 0; ci < 64; ci++) {
        const float* xrow = Xs + ci * 258 + tx;
        const float* wcol = Ws + ty * 4 * 192 + ci * 3;
        #pragma unroll
        for (int k = 0; k < 3; k++) {
            float xv[8], wv[4];
            #pragma unroll
            for (int jc = 0; jc < 8; jc++) xv[jc] = xrow[32 * jc + k];
            #pragma unroll
            for (int jr = 0; jr < 4; jr++) wv[jr] = wcol[jr * 192 + k];
            #pragma unroll
            for (int jr = 0; jr < 4; jr++)
                #pragma unroll
                for (int jc = 0; jc < 8; jc++)
                    acc[jr][jc] += wv[jr] * xv[jc];
        }
    }
    __syncthreads();
    #pragma unroll
    for (int jr = 0; jr < 4; jr++)
        #pragma unroll
        for (int jc = 0; jc < 8; jc++)
            St[(tx + 32 * jc) * 33 + ty * 4 + jr] = acc[jr][jc];
    __syncthreads();
    float* dst = outT + (long)b * 256 * 256 + r0;
    for (int i = tid; i < 32 * 256; i += 256) {
        int l = i >> 5, rr = i & 31;
        dst[l * 256 + rr] = St[l * 33 + rr];
    }
}

// ===== fused lrelu + dilated conv, D templated (R10 proven) =================
template<int D>
__global__ void __launch_bounds__(256) k_dconv(const float* __restrict__ hin,
        const float* __restrict__ w, const float* __restrict__ bias,
        float* __restrict__ out) {
    extern __shared__ float sm[];
    const int PITCH = 312;
    float* Xs = sm;                  // 32*312
    float* Ws = sm + 32 * PITCH;     // 3072
    int b = blockIdx.y;
    int t0 = blockIdx.x * 256;
    int tid = threadIdx.y * 32 + threadIdx.x;
    const int W2 = 256 + 2 * D;
    const float* hb = hin + (long)b * 32 * T_FULL;
    for (int i = tid; i < 32 * W2; i += 256) {
        int ci = i / W2, p = i - ci * W2;
        int t = t0 - D + p;
        float v = ((unsigned)t < (unsigned)T_FULL) ? hb[(long)ci * T_FULL + t] : 0.f;
        Xs[ci * PITCH + p] = lrelu(v);
    }
    for (int i = tid; i < 3072; i += 256) Ws[i] = w[i];
    __syncthreads();
    int tx = threadIdx.x, ty = threadIdx.y;   // ty in 0..7
    u64t acc2[4][4];
    #pragma unroll
    for (int jr = 0; jr < 4; jr++)
        #pragma unroll
        for (int q = 0; q < 4; q++) acc2[jr][q] = 0ull;
    for (int ci = 0; ci < 32; ci++) {
        const float* xrow = Xs + ci * PITCH + tx;
        const float* wrow = Ws + (ty * 4) * 96 + ci * 3;
        #pragma unroll
        for (int k = 0; k < 3; k++) {
            u64t x2[4];
            #pragma unroll
            for (int q = 0; q < 4; q++)
                x2[q] = pk2(xrow[64 * q + k * D], xrow[64 * q + 32 + k * D]);
            #pragma unroll
            for (int jr = 0; jr < 4; jr++) {
                float wv = wrow[jr * 96 + k];
                u64t w2 = pk2(wv, wv);
                #pragma unroll
                for (int q = 0; q < 4; q++)
                    acc2[jr][q] = ffma2(w2, x2[q], acc2[jr][q]);
            }
        }
    }
    #pragma unroll
    for (int jr = 0; jr < 4; jr++) {
        int co = ty * 4 + jr;
        float bv = bias[co];
        float* ob = out + ((long)(b * 32 + co)) * T_FULL + t0 + tx;
        #pragma unroll
        for (int q = 0; q < 4; q++) {
            float lo, hi;
            upk2(acc2[jr][q], lo, hi);
            ob[64 * q]      = lrelu(lo + bv);
            ob[64 * q + 32] = lrelu(hi + bv);
        }
    }
}

// ===== LVC: 512 threads (R9 proven mainloop) + 2-MUFU tanh.approx epilogue ==
__global__ void __launch_bounds__(512) k_lvc(const float* __restrict__ y,
        const float* __restrict__ khT, const float* __restrict__ bhT,
        const float* __restrict__ res, float* __restrict__ out, int layer) {
    extern __shared__ float sm[];
    float* Ks = sm;             // 6144
    float* Xs = sm + 6144;      // 32*258
    float* Bs = Xs + 32 * 258;  // 64
    int b = blockIdx.y, l = blockIdx.x;
    int tid = threadIdx.y * 32 + threadIdx.x;
    const float* ksrc = khT + ((long)(b * 256 + l)) * KC + layer * 6144;
    for (int i = tid; i < 6144; i += 512) Ks[i] = ksrc[i];
    const float* yb = y + (long)b * 32 * T_FULL;
    int tbase = l * 256 - 1;
    for (int i = tid; i < 32 * 258; i += 512) {
        int ci = i / 258, p = i - ci * 258;
        int t = tbase + p;
        Xs[i] = ((unsigned)t < (unsigned)T_FULL) ? yb[(long)ci * T_FULL + t] : 0.f;
    }
    if (tid < 64) Bs[tid] = bhT[((long)(b * 256 + l)) * 256 + layer * 64 + tid];
    __syncthreads();
    int tx = threadIdx.x, ty = threadIdx.y;   // ty in 0..15
    u64t a2A[2][4], a2B[2][4];
    #pragma unroll
    for (int jr = 0; jr < 2; jr++) {
        int o = ty * 2 + jr;
        u64t bA = pk2(Bs[o], Bs[o]);
        u64t bB = pk2(Bs[o + 32], Bs[o + 32]);
        #pragma unroll
        for (int q = 0; q < 4; q++) { a2A[jr][q] = bA; a2B[jr][q] = bB; }
    }
    for (int ci = 0; ci < 32; ci++) {
        const float* xrow = Xs + ci * 258 + tx;
        const float* krow = Ks + ci * 192 + ty * 6;      // o*3 = ty*6 + jr*3
        #pragma unroll
        for (int k = 0; k < 3; k++) {
            u64t x2[4];
            #pragma unroll
            for (int q = 0; q < 4; q++)
                x2[q] = pk2(xrow[64 * q + k], xrow[64 * q + 32 + k]);
            #pragma unroll
            for (int jr = 0; jr < 2; jr++) {
                float wa = krow[jr * 3 + k];
                float wb = krow[96 + jr * 3 + k];        // (o+32)*3 = o*3 + 96
                u64t wA = pk2(wa, wa), wB = pk2(wb, wb);
                #pragma unroll
                for (int q = 0; q < 4; q++) {
                    a2A[jr][q] = ffma2(wA, x2[q], a2A[jr][q]);
                    a2B[jr][q] = ffma2(wB, x2[q], a2B[jr][q]);
                }
            }
        }
    }
    #pragma unroll
    for (int jr = 0; jr < 2; jr++) {
        int co = ty * 2 + jr;
        const float* rb = res + ((long)(b * 32 + co)) * T_FULL + l * 256 + tx;
        float* ob = out + ((long)(b * 32 + co)) * T_FULL + l * 256 + tx;
        #pragma unroll
        for (int q = 0; q < 4; q++) {
            float aL, aH, cL, cH;
            upk2(a2A[jr][q], aL, aH);
            upk2(a2B[jr][q], cL, cH);
            #pragma unroll
            for (int h = 0; h < 2; h++) {
                float a = h ? aH : aL;
                float c = h ? cH : cL;
                // sigmoid(a) = 0.5*tanh(a/2)+0.5 ; tanh via MUFU.TANH
                float sa = fmaf(0.5f, tanh_ap(0.5f * a), 0.5f);
                float th = tanh_ap(c);
                int off = 64 * q + 32 * h;
                ob[off] = sa * th + rb[off];
            }
        }
    }
}

// ---- dconv dispatch (compile-time D) ----------------------------------------
static void launch_dconv(int D, const float* in, const float* w, const float* b,
                         float* out, int smem) {
    dim3 g(256, NB), t(32, 8);
    switch (D) {
        case 1:  k_dconv<1> <<<g, t, smem>>>(in, w, b, out); break;
        case 3:  k_dconv<3> <<<g, t, smem>>>(in, w, b, out); break;
        case 9:  k_dconv<9> <<<g, t, smem>>>(in, w, b, out); break;
        default: k_dconv<27><<<g, t, smem>>>(in, w, b, out); break;
    }
}

// ============================== launcher =====================================
extern "C" void kernel_launch(void* const* d_in, const int* in_sizes, int n_in,
                              void* d_out, int out_size) {
    const float* hidden  = (const float*)d_in[0];
    const float* spec    = (const float*)d_in[1];
    const float* convt_w = (const float*)d_in[2];
    const float* convt_b = (const float*)d_in[3];
    const float* kp_in_w = (const float*)d_in[4];
    const float* kp_in_b = (const float*)d_in[5];
    const float* rb_w1   = (const float*)d_in[6];
    const float* rb_b1   = (const float*)d_in[7];
    const float* rb_w2   = (const float*)d_in[8];
    const float* rb_b2   = (const float*)d_in[9];
    const float* kern_w  = (const float*)d_in[10];
    const float* kern_b  = (const float*)d_in[11];
    const float* bias_w  = (const float*)d_in[12];
    const float* bias_b  = (const float*)d_in[13];
    const float* lvc_w   = (const float*)d_in[14];
    const float* lvc_b   = (const float*)d_in[15];
    float* out = (float*)d_out;

    float *hA, *hB, *yb, *kp0, *khT, *bhT;
    cudaGetSymbolAddress((void**)&hA,  g_hA);
    cudaGetSymbolAddress((void**)&hB,  g_hB);
    cudaGetSymbolAddress((void**)&yb,  g_y);
    cudaGetSymbolAddress((void**)&kp0, g_kp0);
    cudaGetSymbolAddress((void**)&khT, g_kh);
    cudaGetSymbolAddress((void**)&bhT, g_bh);

    const int SMEM_KERN = (64*258 + 64*192) * 4;     // 115200 (St aliased)
    const int SMEM_BG   = (64*258 + 32*192) * 4;     // 90624
    const int SMEM_DC   = (32*312 + 3072) * 4;       // 52224
    const int SMEM_LVC  = (6144 + 32*258 + 64) * 4;  // 57856
    cudaFuncSetAttribute(k_kern,  cudaFuncAttributeMaxDynamicSharedMemorySize, SMEM_KERN);
    cudaFuncSetAttribute(k_biasg, cudaFuncAttributeMaxDynamicSharedMemorySize, SMEM_BG);
    cudaFuncSetAttribute(k_dconv<1>,  cudaFuncAttributeMaxDynamicSharedMemorySize, SMEM_DC);
    cudaFuncSetAttribute(k_dconv<3>,  cudaFuncAttributeMaxDynamicSharedMemorySize, SMEM_DC);
    cudaFuncSetAttribute(k_dconv<9>,  cudaFuncAttributeMaxDynamicSharedMemorySize, SMEM_DC);
    cudaFuncSetAttribute(k_dconv<27>, cudaFuncAttributeMaxDynamicSharedMemorySize, SMEM_DC);
    cudaFuncSetAttribute(k_lvc,   cudaFuncAttributeMaxDynamicSharedMemorySize, SMEM_LVC);

    // #1..#2
    k_convt<<<(NB*CH*8192)/256, 256>>>(hidden, convt_w, convt_b, hA);
    k_kpf<<<dim3(16, NB), 256>>>(spec, kp_in_w, kp_in_b, rb_w1, rb_b1, rb_w2, rb_b2, kp0);
    // #3: dconv layer 0 (needs only hA)
    launch_dconv(1, hA, lvc_w, lvc_b, yb, SMEM_DC);
    // #4: kern conv (profiled slot)
    k_kern<<<dim3(KC/64, NB), dim3(32, 16), SMEM_KERN>>>(kp0, kern_w, kern_b, khT);
    // #5: bias conv
    k_biasg<<<dim3(8, NB), dim3(32, 8), SMEM_BG>>>(kp0, bias_w, bias_b, bhT);
    // #6: lvc layer 0
    k_lvc<<<dim3(256, NB), dim3(32, 16), SMEM_LVC>>>(yb, khT, bhT, hA, hB, 0);

    const int DIL[4] = {1, 3, 9, 27};
    const float* cur = hB;
    for (int i = 1; i < 4; i++) {
        launch_dconv(DIL[i], cur, lvc_w + i*3072, lvc_b + i*32, yb, SMEM_DC);
        float* nxt = (i == 3) ? out : ((i & 1) ? hA : hB);
        k_lvc<<<dim3(256, NB), dim3(32, 16), SMEM_LVC>>>(yb, khT, bhT, cur, nxt, i);
        cur = nxt;
    }
}